// round 7
// baseline (speedup 1.0000x reference)
#include <cuda_runtime.h>
#include <cstdint>

#define N_NODES 50000
#define D_IN    128
#define D_H     128
#define D_Z2    64
#define D_Z     32
#define MAX_E   800000

// -------- device scratch --------
__device__ __align__(16) float d_dinv[N_NODES];
__device__ __align__(16) int   d_cnt [N_NODES];
__device__ __align__(16) int   d_cur [N_NODES];
__device__ __align__(16) int   d_rs  [N_NODES + 1];
__device__ __align__(16) int   d_csr [MAX_E];
__device__ __align__(16) float d_g1  [N_NODES * D_H];
__device__ __align__(16) float d_h   [N_NODES * D_H];
__device__ __align__(16) float d_g2  [N_NODES * D_Z2];
__device__ __align__(16) float d_Wcat[D_H * D_Z2];

// -------- helpers --------
__device__ __forceinline__ uint32_t tf32_hi(float x) {
    uint32_t u;
    asm("cvt.rna.tf32.f32 %0, %1;" : "=r"(u) : "f"(x));
    return u;
}
__device__ __forceinline__ void tf32_split(float x, uint32_t& hi, uint32_t& lo) {
    hi = tf32_hi(x);
    lo = tf32_hi(x - __uint_as_float(hi));
}
__device__ __forceinline__ void mma_tf32(float c[4], const uint32_t a[4], const uint32_t b[2]) {
    asm volatile(
        "mma.sync.aligned.m16n8k8.row.col.f32.tf32.tf32.f32 "
        "{%0,%1,%2,%3}, {%4,%5,%6,%7}, {%8,%9}, {%0,%1,%2,%3};"
        : "+f"(c[0]), "+f"(c[1]), "+f"(c[2]), "+f"(c[3])
        : "r"(a[0]), "r"(a[1]), "r"(a[2]), "r"(a[3]), "r"(b[0]), "r"(b[1]));
}

// -------- CSR build --------
__global__ void zero_int_kernel(int* __restrict__ a, int n) {
    int i = blockIdx.x * blockDim.x + threadIdx.x;
    if (i < n) a[i] = 0;
}

__global__ void hist2_kernel(int* __restrict__ cnt,
                             const int* __restrict__ dst1, int E1,
                             const int* __restrict__ dst2, int E2) {
    int i = blockIdx.x * blockDim.x + threadIdx.x;
    if (i < E1 + E2) {
        int d = (i < E1) ? dst1[i] : dst2[i - E1];
        atomicAdd(&cnt[d], 1);
    }
}

// single-block scan: rs (exclusive), cur = rs copy, dinv = rsqrt(cnt+1)
__global__ void scan_kernel(const int* __restrict__ cnt, int* __restrict__ rs,
                            int* __restrict__ cur, float* __restrict__ dinv, int n) {
    const int T = 1024;
    __shared__ int sums[T];
    int t = threadIdx.x;
    int C = (n + T - 1) / T;
    int lo = t * C, hi = min(lo + C, n);
    int s = 0;
    for (int i = lo; i < hi; i++) s += cnt[i];
    sums[t] = s;
    __syncthreads();
    for (int off = 1; off < T; off <<= 1) {
        int tmp = (t >= off) ? sums[t - off] : 0;
        __syncthreads();
        sums[t] += tmp;
        __syncthreads();
    }
    int run = sums[t] - s;
    for (int i = lo; i < hi; i++) {
        rs[i] = run;
        cur[i] = run;
        dinv[i] = rsqrtf((float)(cnt[i] + 1));
        run += cnt[i];
    }
    if (t == T - 1) rs[n] = sums[T - 1];
}

__global__ void scatter2_kernel(const int* __restrict__ src1, const int* __restrict__ dst1, int E1,
                                const int* __restrict__ src2, const int* __restrict__ dst2, int E2,
                                int* __restrict__ cur, int* __restrict__ csr) {
    int i = blockIdx.x * blockDim.x + threadIdx.x;
    if (i < E1 + E2) {
        int s, d;
        if (i < E1) { s = src1[i]; d = dst1[i]; }
        else        { s = src2[i - E1]; d = dst2[i - E1]; }
        int pos = atomicAdd(&cur[d], 1);
        csr[pos] = s;
    }
}

__global__ void wcat_kernel(float* __restrict__ Wcat,
                            const float* __restrict__ Wmu, const float* __restrict__ Wls) {
    int i = blockIdx.x * blockDim.x + threadIdx.x;
    if (i < D_H * D_Z2) {
        int k = i / D_Z2, j = i % D_Z2;
        Wcat[i] = (j < D_Z) ? Wmu[k * D_Z + j] : Wls[k * D_Z + (j - D_Z)];
    }
}

// ==================== 3xTF32 mma.sync GEMM ====================
// CTA: 128 rows x NOUT cols, 256 threads = 8 warps in 4(M) x 2(N) grid.
// Warp tile: 32 x (NOUT/2). K chunked by 32. D = Ahi*Bhi + Ahi*Blo + Alo*Bhi.
// Epilogue: g = D * dinv[row].
template <int NOUT>
__global__ __launch_bounds__(256) void mma_gemm_kernel(
    const float* __restrict__ X, const float* __restrict__ W,
    const float* __restrict__ dinv, float* __restrict__ g, int nrows)
{
    constexpr int WN = NOUT / 2;        // warp N extent: 64 or 32
    constexpr int NT = WN / 8;          // N-tiles per warp: 8 or 4
    constexpr int LDA = 36;             // padded stride (floats), conflict-free frags
    __shared__ float As[128 * LDA];
    __shared__ float Bs[NOUT * LDA];

    const int tid = threadIdx.x;
    const int wid = tid >> 5, lane = tid & 31;
    const int wm = wid & 3, wn = wid >> 2;       // 4 M-warps x 2 N-warps
    const int row0 = blockIdx.x * 128;
    const int qid = lane >> 2, qt = lane & 3;    // quad row / quad thread

    float acc[2][NT][4];
#pragma unroll
    for (int mi = 0; mi < 2; mi++)
#pragma unroll
        for (int ni = 0; ni < NT; ni++)
#pragma unroll
            for (int j = 0; j < 4; j++) acc[mi][ni][j] = 0.0f;

    for (int c = 0; c < 4; c++) {
        // A chunk: 128 rows x 32 k-floats
#pragma unroll
        for (int i = tid; i < 1024; i += 256) {          // 1024 float4
            int r = i >> 3, c4 = (i & 7) * 4;
            float4 v = make_float4(0.f, 0.f, 0.f, 0.f);
            if (row0 + r < nrows)
                v = *reinterpret_cast<const float4*>(X + (size_t)(row0 + r) * 128 + c * 32 + c4);
            *reinterpret_cast<float4*>(&As[r * LDA + c4]) = v;
        }
        // B chunk: NOUT n x 32 k  (Bs[n][k] = W[c*32+k][n])
#pragma unroll
        for (int i = tid; i < NOUT * 32; i += 256) {
            int nn = i % NOUT, kk = i / NOUT;
            Bs[nn * LDA + kk] = W[(size_t)(c * 32 + kk) * NOUT + nn];
        }
        __syncthreads();

#pragma unroll
        for (int ks = 0; ks < 4; ks++) {
            // A fragments for mi = 0,1 (m16k8 each), hi/lo split
            uint32_t ahi[2][4], alo[2][4];
#pragma unroll
            for (int mi = 0; mi < 2; mi++) {
                int r = wm * 32 + mi * 16 + qid;
                int k = ks * 8 + qt;
                tf32_split(As[r * LDA + k],           ahi[mi][0], alo[mi][0]);
                tf32_split(As[(r + 8) * LDA + k],     ahi[mi][1], alo[mi][1]);
                tf32_split(As[r * LDA + k + 4],       ahi[mi][2], alo[mi][2]);
                tf32_split(As[(r + 8) * LDA + k + 4], ahi[mi][3], alo[mi][3]);
            }
#pragma unroll
            for (int ni = 0; ni < NT; ni++) {
                int nn = wn * WN + ni * 8 + qid;
                int k = ks * 8 + qt;
                uint32_t bhi[2], blo[2];
                tf32_split(Bs[nn * LDA + k],     bhi[0], blo[0]);
                tf32_split(Bs[nn * LDA + k + 4], bhi[1], blo[1]);
#pragma unroll
                for (int mi = 0; mi < 2; mi++) {
                    mma_tf32(acc[mi][ni], ahi[mi], blo);
                    mma_tf32(acc[mi][ni], alo[mi], bhi);
                    mma_tf32(acc[mi][ni], ahi[mi], bhi);
                }
            }
        }
        __syncthreads();
    }

    // epilogue: scale rows by dinv, write float2 pairs
#pragma unroll
    for (int mi = 0; mi < 2; mi++) {
        int r0 = row0 + wm * 32 + mi * 16 + qid;
        int r1 = r0 + 8;
        float w0 = (r0 < nrows) ? dinv[r0] : 0.f;
        float w1 = (r1 < nrows) ? dinv[r1] : 0.f;
#pragma unroll
        for (int ni = 0; ni < NT; ni++) {
            int col = wn * WN + ni * 8 + qt * 2;
            if (r0 < nrows) {
                float2 o = make_float2(acc[mi][ni][0] * w0, acc[mi][ni][1] * w0);
                *reinterpret_cast<float2*>(g + (size_t)r0 * NOUT + col) = o;
            }
            if (r1 < nrows) {
                float2 o = make_float2(acc[mi][ni][2] * w1, acc[mi][ni][3] * w1);
                *reinterpret_cast<float2*>(g + (size_t)r1 * NOUT + col) = o;
            }
        }
    }
}

// -------- gather aggregation, layer 1 (F=128), fused bias+relu --------
__global__ __launch_bounds__(256) void agg1_kernel(
    const int* __restrict__ rs, const int* __restrict__ csr,
    const float* __restrict__ g, const float* __restrict__ dinv,
    const float* __restrict__ b1, float* __restrict__ h, int n)
{
    int d = (blockIdx.x * blockDim.x + threadIdx.x) >> 5;
    int lane = threadIdx.x & 31;
    if (d >= n) return;

    const float4* gv = reinterpret_cast<const float4*>(g);
    int col = lane;
    float4 a0 = gv[(size_t)d * 32 + col];
    float4 a1 = make_float4(0.f, 0.f, 0.f, 0.f);

    int e = rs[d], end = rs[d + 1];
    for (; e + 2 <= end; e += 2) {
        int s0 = __ldg(&csr[e]);
        int s1 = __ldg(&csr[e + 1]);
        float4 v0 = gv[(size_t)s0 * 32 + col];
        float4 v1 = gv[(size_t)s1 * 32 + col];
        a0.x += v0.x; a0.y += v0.y; a0.z += v0.z; a0.w += v0.w;
        a1.x += v1.x; a1.y += v1.y; a1.z += v1.z; a1.w += v1.w;
    }
    if (e < end) {
        int s0 = __ldg(&csr[e]);
        float4 v0 = gv[(size_t)s0 * 32 + col];
        a0.x += v0.x; a0.y += v0.y; a0.z += v0.z; a0.w += v0.w;
    }
    float w = dinv[d];
    float4 bb = reinterpret_cast<const float4*>(b1)[col];
    float4 r;
    r.x = fmaxf(fmaf(a0.x + a1.x, w, bb.x), 0.f);
    r.y = fmaxf(fmaf(a0.y + a1.y, w, bb.y), 0.f);
    r.z = fmaxf(fmaf(a0.z + a1.z, w, bb.z), 0.f);
    r.w = fmaxf(fmaf(a0.w + a1.w, w, bb.w), 0.f);
    reinterpret_cast<float4*>(h)[(size_t)d * 32 + col] = r;
}

// -------- gather aggregation, layer 2 (F=64), fused bias + mu/logstd split --------
__global__ __launch_bounds__(256) void agg2_kernel(
    const int* __restrict__ rs, const int* __restrict__ csr,
    const float* __restrict__ g, const float* __restrict__ dinv,
    const float* __restrict__ bmu, const float* __restrict__ bls,
    float* __restrict__ out, int n)
{
    int d = (blockIdx.x * blockDim.x + threadIdx.x) >> 5;
    int lane = threadIdx.x & 31;
    if (d >= n) return;

    const float2* gv = reinterpret_cast<const float2*>(g);
    int col = lane;
    float2 a0 = gv[(size_t)d * 32 + col];
    float2 a1 = make_float2(0.f, 0.f);

    int e = rs[d], end = rs[d + 1];
    for (; e + 2 <= end; e += 2) {
        int s0 = __ldg(&csr[e]);
        int s1 = __ldg(&csr[e + 1]);
        float2 v0 = gv[(size_t)s0 * 32 + col];
        float2 v1 = gv[(size_t)s1 * 32 + col];
        a0.x += v0.x; a0.y += v0.y;
        a1.x += v1.x; a1.y += v1.y;
    }
    if (e < end) {
        int s0 = __ldg(&csr[e]);
        float2 v0 = gv[(size_t)s0 * 32 + col];
        a0.x += v0.x; a0.y += v0.y;
    }
    float w = dinv[d];
    float vx = (a0.x + a1.x) * w;
    float vy = (a0.y + a1.y) * w;
    int c0 = col * 2, c1 = col * 2 + 1;
    if (c0 < D_Z) {
        float2 o = make_float2(vx + bmu[c0], vy + bmu[c1]);
        reinterpret_cast<float2*>(out)[(size_t)d * 16 + col] = o;
    } else {
        float2 o = make_float2(vx + bls[c0 - D_Z], vy + bls[c1 - D_Z]);
        reinterpret_cast<float2*>(out + (size_t)n * D_Z)[(size_t)d * 16 + (col - 16)] = o;
    }
}

extern "C" void kernel_launch(void* const* d_in, const int* in_sizes, int n_in,
                              void* d_out, int out_size)
{
    const float* x    = (const float*)d_in[0];
    const int*   ei1  = (const int*)d_in[1];
    const int*   ei2  = (const int*)d_in[2];
    const float* W1   = (const float*)d_in[3];
    const float* b1   = (const float*)d_in[4];
    const float* Wmu  = (const float*)d_in[5];
    const float* bmu  = (const float*)d_in[6];
    const float* Wls  = (const float*)d_in[7];
    const float* bls  = (const float*)d_in[8];
    float* out = (float*)d_out;

    float *p_dinv, *p_g1, *p_h, *p_g2, *p_Wcat;
    int *p_cnt, *p_cur, *p_rs, *p_csr;
    cudaGetSymbolAddress((void**)&p_dinv, d_dinv);
    cudaGetSymbolAddress((void**)&p_cnt,  d_cnt);
    cudaGetSymbolAddress((void**)&p_cur,  d_cur);
    cudaGetSymbolAddress((void**)&p_rs,   d_rs);
    cudaGetSymbolAddress((void**)&p_csr,  d_csr);
    cudaGetSymbolAddress((void**)&p_g1,   d_g1);
    cudaGetSymbolAddress((void**)&p_h,    d_h);
    cudaGetSymbolAddress((void**)&p_g2,   d_g2);
    cudaGetSymbolAddress((void**)&p_Wcat, d_Wcat);

    const int n  = in_sizes[0] / D_IN;   // 50000
    const int E1 = in_sizes[1] / 2;      // 600000
    const int E2 = in_sizes[2] / 2;      // 200000
    const int* src1 = ei1; const int* dst1 = ei1 + E1;
    const int* src2 = ei2; const int* dst2 = ei2 + E2;

    const int T = 256;
    // ---- CSR build ----
    zero_int_kernel<<<(n + T - 1) / T, T>>>(p_cnt, n);
    hist2_kernel<<<(E1 + E2 + T - 1) / T, T>>>(p_cnt, dst1, E1, dst2, E2);
    scan_kernel<<<1, 1024>>>(p_cnt, p_rs, p_cur, p_dinv, n);
    scatter2_kernel<<<(E1 + E2 + T - 1) / T, T>>>(src1, dst1, E1, src2, dst2, E2, p_cur, p_csr);
    wcat_kernel<<<(D_H * D_Z2 + T - 1) / T, T>>>(p_Wcat, Wmu, Wls);

    // ---- layer 1 ----
    int tiles = (n + 127) / 128;    // 391
    mma_gemm_kernel<128><<<tiles, 256>>>(x, W1, p_dinv, p_g1, n);
    agg1_kernel<<<(n * 32 + T - 1) / T, T>>>(p_rs, p_csr, p_g1, p_dinv, b1, p_h, n);

    // ---- layer 2 (fused heads) ----
    mma_gemm_kernel<64><<<tiles, 256>>>(p_h, p_Wcat, p_dinv, p_g2, n);
    agg2_kernel<<<(n * 32 + T - 1) / T, T>>>(p_rs, p_csr, p_g2, p_dinv, bmu, bls, out, n);
}